// round 1
// baseline (speedup 1.0000x reference)
#include <cuda_runtime.h>
#include <cstddef>

// Problem dimensions (fixed by the reference)
#define M1 16384      // b*t*s = 16*4*256
#define K1 512        // d
#define N1 2048       // hidden
#define K2 2048
#define N2 512
#define HID 2048
#define N_SPIKES 33554432.0f  // 16*4*256*2048 = 2^25

// Scratch: h and spikes (device globals; no allocation allowed)
__device__ float g_h[(size_t)M1 * N1];
__device__ float g_spk[(size_t)M1 * N1];
__device__ int   g_count;

// ---------------------------------------------------------------------------
// SGEMM (NT): C[M,N] = A[M,K] * B[N,K]^T, all row-major, fp32.
// 128x128 tile, BK=16, 256 threads, 8x8 per thread.
// ---------------------------------------------------------------------------
__global__ __launch_bounds__(256, 2) void sgemm_nt(const float* __restrict__ A,
                                                   const float* __restrict__ B,
                                                   float* __restrict__ C,
                                                   int M, int N, int K) {
    __shared__ float As[16][132];
    __shared__ float Bs[16][132];

    const int t  = threadIdx.x;
    const int tx = t & 15;          // 0..15 -> 8 cols each
    const int ty = t >> 4;          // 0..15 -> 8 rows each
    const int lrow = t >> 2;        // 0..63 (load row, +64 for second half)
    const int lcol = (t & 3) << 2;  // 0,4,8,12 (k offset within BK)

    const float* Ab = A + (size_t)blockIdx.y * 128 * K;
    const float* Bb = B + (size_t)blockIdx.x * 128 * K;

    float acc[8][8];
#pragma unroll
    for (int i = 0; i < 8; i++)
#pragma unroll
        for (int j = 0; j < 8; j++) acc[i][j] = 0.0f;

    for (int k0 = 0; k0 < K; k0 += 16) {
        float4 a0 = *(const float4*)(Ab + (size_t)lrow * K + k0 + lcol);
        float4 a1 = *(const float4*)(Ab + (size_t)(lrow + 64) * K + k0 + lcol);
        float4 b0 = *(const float4*)(Bb + (size_t)lrow * K + k0 + lcol);
        float4 b1 = *(const float4*)(Bb + (size_t)(lrow + 64) * K + k0 + lcol);

        __syncthreads();
        As[lcol + 0][lrow] = a0.x; As[lcol + 1][lrow] = a0.y;
        As[lcol + 2][lrow] = a0.z; As[lcol + 3][lrow] = a0.w;
        As[lcol + 0][lrow + 64] = a1.x; As[lcol + 1][lrow + 64] = a1.y;
        As[lcol + 2][lrow + 64] = a1.z; As[lcol + 3][lrow + 64] = a1.w;
        Bs[lcol + 0][lrow] = b0.x; Bs[lcol + 1][lrow] = b0.y;
        Bs[lcol + 2][lrow] = b0.z; Bs[lcol + 3][lrow] = b0.w;
        Bs[lcol + 0][lrow + 64] = b1.x; Bs[lcol + 1][lrow + 64] = b1.y;
        Bs[lcol + 2][lrow + 64] = b1.z; Bs[lcol + 3][lrow + 64] = b1.w;
        __syncthreads();

#pragma unroll
        for (int k = 0; k < 16; k++) {
            float a[8], b[8];
            *(float4*)(a)     = *(const float4*)(&As[k][ty * 8]);
            *(float4*)(a + 4) = *(const float4*)(&As[k][ty * 8 + 4]);
            *(float4*)(b)     = *(const float4*)(&Bs[k][tx * 8]);
            *(float4*)(b + 4) = *(const float4*)(&Bs[k][tx * 8 + 4]);
#pragma unroll
            for (int i = 0; i < 8; i++)
#pragma unroll
                for (int j = 0; j < 8; j++)
                    acc[i][j] = fmaf(a[i], b[j], acc[i][j]);
        }
    }

    float* Cb = C + (size_t)(blockIdx.y * 128 + ty * 8) * N + blockIdx.x * 128 + tx * 8;
#pragma unroll
    for (int i = 0; i < 8; i++) {
        *(float4*)(Cb + (size_t)i * N)     = *(float4*)(&acc[i][0]);
        *(float4*)(Cb + (size_t)i * N + 4) = *(float4*)(&acc[i][4]);
    }
}

// ---------------------------------------------------------------------------
// LIF scan over t=4: v = 0.95*v + h; spk = (v-1)>0; v *= (1-spk).
// One thread per (b,s,hidden). Also counts spikes (exact integer).
// ---------------------------------------------------------------------------
__global__ void zero_count_kernel() { g_count = 0; }

__global__ __launch_bounds__(256) void lif_kernel() {
    int idx = blockIdx.x * blockDim.x + threadIdx.x;  // 0 .. 4096*2048-1
    int j   = idx & (HID - 1);
    int row = idx >> 11;          // b*256 + s
    int b   = row >> 8;
    int s   = row & 255;
    size_t base = ((size_t)b * 1024 + s) * HID + j;   // (b, t=0, s) row
    const size_t tstride = (size_t)256 * HID;

    float v = 0.0f;
    int c = 0;
#pragma unroll
    for (int tt = 0; tt < 4; tt++) {
        float inp = g_h[base + tt * tstride];
        v = fmaf(0.95f, v, inp);
        bool fire = (v - 1.0f) > 0.0f;
        float sp = fire ? 1.0f : 0.0f;
        g_spk[base + tt * tstride] = sp;
        c += fire ? 1 : 0;
        v *= (1.0f - sp);
    }
#pragma unroll
    for (int o = 16; o > 0; o >>= 1) c += __shfl_down_sync(0xffffffffu, c, o);
    if ((threadIdx.x & 31) == 0) atomicAdd(&g_count, c);
}

__global__ void write_rate_kernel(float* __restrict__ out, int pos) {
    // count / 2^25 is exact in fp32 (division by power of two)
    out[pos] = (float)g_count * (1.0f / N_SPIKES);
}

// ---------------------------------------------------------------------------
extern "C" void kernel_launch(void* const* d_in, const int* in_sizes, int n_in,
                              void* d_out, int out_size) {
    const float* x  = (const float*)d_in[0];  // (16,4,256,512)
    const float* w1 = (const float*)d_in[1];  // (2048,512)
    const float* w2 = (const float*)d_in[2];  // (512,2048)
    float* out = (float*)d_out;               // 16*4*256*512 elems + rate

    float* h_ptr   = nullptr;
    float* spk_ptr = nullptr;
    cudaGetSymbolAddress((void**)&h_ptr, g_h);
    cudaGetSymbolAddress((void**)&spk_ptr, g_spk);

    dim3 blk(256);

    // fc1: h = x @ w1^T   (M=16384, N=2048, K=512)
    sgemm_nt<<<dim3(N1 / 128, M1 / 128), blk>>>(x, w1, h_ptr, M1, N1, K1);

    // LIF scan + spike count
    zero_count_kernel<<<1, 1>>>();
    lif_kernel<<<(4096 * HID) / 256, blk>>>();

    // fc2: out = spk @ w2^T   (M=16384, N=512, K=2048)
    sgemm_nt<<<dim3(N2 / 128, M1 / 128), blk>>>(spk_ptr, w2, out, M1, N2, K2);

    // rate scalar at the tail of the output buffer
    write_rate_kernel<<<1, 1>>>(out, out_size - 1);
}

// round 5
// speedup vs baseline: 2.1222x; 2.1222x over previous
#include <cuda_runtime.h>
#include <cuda_fp16.h>
#include <cstdint>
#include <cstddef>

// Problem dims (fixed)
#define M1 16384      // b*t*s = 16*4*256
#define K1 512        // d
#define N1 2048       // hidden
#define N2 512
#define HID 2048
#define N_SPIKES 33554432.0f  // 2^25

#define KE1 1536      // 3*K1  (x0|x0|x1 vs w0|w1|w0)
#define KE2 4096      // 2*HID (spk|spk vs w2_0|w2_1)
#define WSCALE 64.0f
#define INV_WSCALE (1.0f / 64.0f)

#define TAU 1e-3f     // borderline window for exact fixup
#define FCAP (1 << 22)

// ---------------------------------------------------------------------------
// Device scratch (no allocation allowed)
// ---------------------------------------------------------------------------
__device__ float  g_h[(size_t)M1 * N1];            // fc1 output (approx h, fp32)
__device__ __half g_a1[(size_t)M1 * KE1];          // [x0|x0|x1]
__device__ __half g_b1[(size_t)N1 * KE1];          // [w1_0|w1_1|w1_0] (x64)
__device__ __half g_a2[(size_t)M1 * KE2];          // [spk|spk]
__device__ __half g_b2[(size_t)N2 * KE2];          // [w2_0|w2_1]     (x64)
__device__ int    g_count;
__device__ int    g_nflag;
__device__ int    g_flag[FCAP];

// ---------------------------------------------------------------------------
// PTX helpers (baseline sm_80+ ISA: cp.async / ldmatrix / mma.sync)
// ---------------------------------------------------------------------------
__device__ __forceinline__ uint32_t smem_u32(const void* p) {
    uint32_t a;
    asm("{ .reg .u64 t; cvta.to.shared.u64 t, %1; cvt.u32.u64 %0, t; }" : "=r"(a) : "l"(p));
    return a;
}
__device__ __forceinline__ void cp16(uint32_t saddr, const void* g) {
    asm volatile("cp.async.cg.shared.global [%0], [%1], 16;" :: "r"(saddr), "l"(g));
}
__device__ __forceinline__ void ldm_x4(uint32_t* r, uint32_t addr) {
    asm volatile("ldmatrix.sync.aligned.m8n8.x4.shared.b16 {%0,%1,%2,%3}, [%4];"
        : "=r"(r[0]), "=r"(r[1]), "=r"(r[2]), "=r"(r[3]) : "r"(addr));
}
__device__ __forceinline__ void mma16816(float* c, const uint32_t* a, uint32_t b0, uint32_t b1) {
    asm volatile("mma.sync.aligned.m16n8k16.row.col.f32.f16.f16.f32 "
        "{%0,%1,%2,%3}, {%4,%5,%6,%7}, {%8,%9}, {%0,%1,%2,%3};"
        : "+f"(c[0]), "+f"(c[1]), "+f"(c[2]), "+f"(c[3])
        : "r"(a[0]), "r"(a[1]), "r"(a[2]), "r"(a[3]), "r"(b0), "r"(b1));
}

// ---------------------------------------------------------------------------
// HGEMM (NT): C[M,N] = (A[M,K] @ B[N,K]^T) * cscale, fp16 in / fp32 out.
// 128x128x64 tiles, 3-stage cp.async pipeline, 8 warps (32x64 per warp).
// ---------------------------------------------------------------------------
#define BM 128
#define BN 128
#define BK 64
#define STAGES 3
#define A_STAGE_BYTES (BM * BK * 2)                 // 16384
#define STAGE_BYTES   (A_STAGE_BYTES + BN * BK * 2) // 32768
#define SMEM_TOTAL    (STAGES * STAGE_BYTES)        // 98304

__device__ __forceinline__ void load_stage(uint32_t s_stage, const __half* Ag,
                                           const __half* Bg, int K, int k0, int tid) {
#pragma unroll
    for (int i = 0; i < 4; i++) {
        int c = tid + i * 256;           // 0..1023
        int row = c >> 3, kc = c & 7;
        uint32_t so = s_stage + row * 128 + ((kc ^ (row & 7)) << 4);
        cp16(so, Ag + (long)row * K + k0 + kc * 8);
    }
#pragma unroll
    for (int i = 0; i < 4; i++) {
        int c = tid + i * 256;
        int row = c >> 3, kc = c & 7;
        uint32_t so = s_stage + A_STAGE_BYTES + row * 128 + ((kc ^ (row & 7)) << 4);
        cp16(so, Bg + (long)row * K + k0 + kc * 8);
    }
}

__global__ __launch_bounds__(256, 2) void hgemm(const __half* __restrict__ A,
                                                const __half* __restrict__ B,
                                                float* __restrict__ C,
                                                int N, int K, float cscale) {
    extern __shared__ char sm[];
    const uint32_t s_base = smem_u32(sm);
    const int tid = threadIdx.x;
    const int wid = tid >> 5, lane = tid & 31;
    const int wm = wid & 3;          // warp row block (32 rows)
    const int wn = wid >> 2;         // warp col block (64 cols)
    const long bm = (long)blockIdx.y * BM;
    const long bn = (long)blockIdx.x * BN;

    const __half* Ag = A + bm * K;
    const __half* Bg = B + bn * K;

    float acc[2][8][4];
#pragma unroll
    for (int mt = 0; mt < 2; mt++)
#pragma unroll
        for (int nt = 0; nt < 8; nt++)
#pragma unroll
            for (int i = 0; i < 4; i++) acc[mt][nt][i] = 0.0f;

    const int iters = K / BK;

    load_stage(s_base, Ag, Bg, K, 0, tid);
    asm volatile("cp.async.commit_group;" ::: "memory");
    load_stage(s_base + STAGE_BYTES, Ag, Bg, K, BK, tid);
    asm volatile("cp.async.commit_group;" ::: "memory");

    for (int it = 0; it < iters; it++) {
        asm volatile("cp.async.wait_group 1;" ::: "memory");
        __syncthreads();

        const int nst = it + 2;
        if (nst < iters)
            load_stage(s_base + (nst % STAGES) * STAGE_BYTES, Ag, Bg, K, nst * BK, tid);
        asm volatile("cp.async.commit_group;" ::: "memory");

        const uint32_t sa = s_base + (it % STAGES) * STAGE_BYTES;
        const uint32_t sb = sa + A_STAGE_BYTES;

#pragma unroll
        for (int ks = 0; ks < 4; ks++) {
            const int kch = (ks << 1) + (lane >> 4);   // k16-step -> 8-elem chunk
            uint32_t ar[2][4];
#pragma unroll
            for (int mt = 0; mt < 2; mt++) {
                int row = wm * 32 + mt * 16 + (lane & 15);
                ldm_x4(ar[mt], sa + row * 128 + ((kch ^ (row & 7)) << 4));
            }
            uint32_t br[4][4];
#pragma unroll
            for (int np = 0; np < 4; np++) {
                int row = wn * 64 + np * 16 + (lane & 15);
                ldm_x4(br[np], sb + row * 128 + ((kch ^ (row & 7)) << 4));
            }
#pragma unroll
            for (int mt = 0; mt < 2; mt++)
#pragma unroll
                for (int nt = 0; nt < 8; nt++)
                    mma16816(acc[mt][nt], ar[mt], br[nt >> 1][nt & 1], br[nt >> 1][(nt & 1) + 2]);
        }
    }

    // epilogue: scaled fp32 stores
#pragma unroll
    for (int mt = 0; mt < 2; mt++) {
#pragma unroll
        for (int nt = 0; nt < 8; nt++) {
            long r = bm + wm * 32 + mt * 16 + (lane >> 2);
            long c = bn + wn * 64 + nt * 8 + (lane & 3) * 2;
            float2 v0 = make_float2(acc[mt][nt][0] * cscale, acc[mt][nt][1] * cscale);
            float2 v1 = make_float2(acc[mt][nt][2] * cscale, acc[mt][nt][3] * cscale);
            *(float2*)(C + r * N + c) = v0;
            *(float2*)(C + (r + 8) * N + c) = v1;
        }
    }
}

// ---------------------------------------------------------------------------
// fp32 -> 2-way fp16 splits, expanded into K-concatenated operand buffers
// ---------------------------------------------------------------------------
__global__ __launch_bounds__(256) void split_x_kernel(const float* __restrict__ x,
                                                      __half* __restrict__ Aext) {
    int i = blockIdx.x * blockDim.x + threadIdx.x;     // M1*K1 elements
    if (i >= M1 * K1) return;
    int m = i >> 9, k = i & 511;
    float v = x[i];
    __half h0 = __float2half_rn(v);
    __half h1 = __float2half_rn(v - __half2float(h0));
    size_t ro = (size_t)m * KE1;
    Aext[ro + k] = h0;           // pairs with w0
    Aext[ro + 512 + k] = h0;     // pairs with w1
    Aext[ro + 1024 + k] = h1;    // pairs with w0
}

__global__ __launch_bounds__(256) void split_w1_kernel(const float* __restrict__ w,
                                                       __half* __restrict__ Bext) {
    int i = blockIdx.x * blockDim.x + threadIdx.x;     // N1*K1 elements
    if (i >= N1 * K1) return;
    int n = i >> 9, k = i & 511;
    float v = w[i] * WSCALE;
    __half h0 = __float2half_rn(v);
    __half h1 = __float2half_rn(v - __half2float(h0));
    size_t ro = (size_t)n * KE1;
    Bext[ro + k] = h0;
    Bext[ro + 512 + k] = h1;
    Bext[ro + 1024 + k] = h0;
}

__global__ __launch_bounds__(256) void split_w2_kernel(const float* __restrict__ w,
                                                       __half* __restrict__ Bext) {
    int i = blockIdx.x * blockDim.x + threadIdx.x;     // N2*HID elements
    if (i >= N2 * HID) return;
    int n = i >> 11, k = i & 2047;
    float v = w[i] * WSCALE;
    __half h0 = __float2half_rn(v);
    __half h1 = __float2half_rn(v - __half2float(h0));
    size_t ro = (size_t)n * KE2;
    Bext[ro + k] = h0;
    Bext[ro + 2048 + k] = h1;
}

// ---------------------------------------------------------------------------
// LIF scan (t=4) on approx h, with borderline flagging.
// Unflagged decisions are provably exact (|v-1| >= TAU >> delta_v).
// ---------------------------------------------------------------------------
__global__ void zero_count_kernel() { g_count = 0; g_nflag = 0; }

__global__ __launch_bounds__(256) void lif_kernel() {
    int idx = blockIdx.x * blockDim.x + threadIdx.x;   // 0 .. 4096*2048-1
    int j   = idx & (HID - 1);
    int row = idx >> 11;
    int b   = row >> 8;
    int s   = row & 255;
    size_t hbase = ((size_t)b * 1024 + s) * HID + j;   // h: (b,t,s,hid)
    size_t abase = ((size_t)b * 1024 + s) * KE2 + j;   // a2: (b,t,s, 2*hid)
    const size_t hstride = (size_t)256 * HID;
    const size_t astride = (size_t)256 * KE2;

    const __half one  = __float2half_rn(1.0f);
    const __half zero = __float2half_rn(0.0f);

    float v = 0.0f;
    int c = 0;
    bool flagged = false;
#pragma unroll
    for (int tt = 0; tt < 4; tt++) {
        float inp = g_h[hbase + tt * hstride];
        v = fmaf(0.95f, v, inp);
        flagged |= fabsf(v - 1.0f) < TAU;
        bool fire = (v - 1.0f) > 0.0f;
        __half sp = fire ? one : zero;
        g_a2[abase + tt * astride] = sp;
        g_a2[abase + tt * astride + HID] = sp;
        c += fire ? 1 : 0;
        v = fire ? 0.0f : v;
    }
    if (flagged) {
        c = 0;  // counted exactly in fixup
        int slot = atomicAdd(&g_nflag, 1);
        if (slot < FCAP) g_flag[slot] = idx;
    }
#pragma unroll
    for (int o = 16; o > 0; o >>= 1) c += __shfl_down_sync(0xffffffffu, c, o);
    if ((threadIdx.x & 31) == 0 && c) atomicAdd(&g_count, c);
}

// ---------------------------------------------------------------------------
// Exact fixup for flagged neurons: bit-identical arithmetic to the R1 kernel
// (sequential ascending-k fp32 fmaf), which produced 0 flips vs reference.
// ---------------------------------------------------------------------------
__global__ __launch_bounds__(128) void fixup_kernel(const float* __restrict__ x,
                                                    const float* __restrict__ w1) {
    int n = g_nflag;
    if (n > FCAP) n = FCAP;
    const int stride = gridDim.x * blockDim.x;
    const __half one  = __float2half_rn(1.0f);
    const __half zero = __float2half_rn(0.0f);

    for (int i = blockIdx.x * blockDim.x + threadIdx.x; i < n; i += stride) {
        int idx = g_flag[i];
        int j   = idx & (HID - 1);
        int row = idx >> 11;
        int b   = row >> 8;
        int s   = row & 255;
        const float4* wrow = (const float4*)(w1 + (size_t)j * K1);
        size_t abase = ((size_t)b * 1024 + s) * KE2 + j;
        const size_t astride = (size_t)256 * KE2;

        float v = 0.0f;
        int c = 0;
#pragma unroll
        for (int tt = 0; tt < 4; tt++) {
            const float4* xrow = (const float4*)(x + (((size_t)b * 4 + tt) * 256 + s) * K1);
            float h = 0.0f;
            for (int k = 0; k < K1 / 4; k++) {
                float4 xv = __ldg(xrow + k);
                float4 wv = __ldg(wrow + k);
                h = fmaf(xv.x, wv.x, h);
                h = fmaf(xv.y, wv.y, h);
                h = fmaf(xv.z, wv.z, h);
                h = fmaf(xv.w, wv.w, h);
            }
            v = fmaf(0.95f, v, h);
            bool fire = (v - 1.0f) > 0.0f;
            __half sp = fire ? one : zero;
            g_a2[abase + tt * astride] = sp;
            g_a2[abase + tt * astride + HID] = sp;
            c += fire ? 1 : 0;
            v = fire ? 0.0f : v;
        }
        if (c) atomicAdd(&g_count, c);
    }
}

__global__ void write_rate_kernel(float* __restrict__ out, int pos) {
    out[pos] = (float)g_count * (1.0f / N_SPIKES);  // exact: count / 2^25
}

// ---------------------------------------------------------------------------
extern "C" void kernel_launch(void* const* d_in, const int* in_sizes, int n_in,
                              void* d_out, int out_size) {
    const float* x  = (const float*)d_in[0];  // (16,4,256,512)
    const float* w1 = (const float*)d_in[1];  // (2048,512)
    const float* w2 = (const float*)d_in[2];  // (512,2048)
    float* out = (float*)d_out;

    float* h_ptr = nullptr;
    __half *a1, *b1, *a2, *b2;
    cudaGetSymbolAddress((void**)&h_ptr, g_h);
    cudaGetSymbolAddress((void**)&a1, g_a1);
    cudaGetSymbolAddress((void**)&b1, g_b1);
    cudaGetSymbolAddress((void**)&a2, g_a2);
    cudaGetSymbolAddress((void**)&b2, g_b2);

    cudaFuncSetAttribute(hgemm, cudaFuncAttributeMaxDynamicSharedMemorySize, SMEM_TOTAL);

    dim3 blk(256);

    // operand splits / expansion
    split_x_kernel<<<(M1 * K1 + 255) / 256, blk>>>(x, a1);
    split_w1_kernel<<<(N1 * K1 + 255) / 256, blk>>>(w1, b1);
    split_w2_kernel<<<(N2 * HID + 255) / 256, blk>>>(w2, b2);

    // fc1: approx h = x @ w1^T  (3 fp16 split products folded into K=1536)
    hgemm<<<dim3(N1 / BN, M1 / BM), blk, SMEM_TOTAL>>>(a1, b1, h_ptr, N1, KE1, INV_WSCALE);

    // LIF scan (flags borderline neurons) + exact fixup for flagged ones
    zero_count_kernel<<<1, 1>>>();
    lif_kernel<<<(4096 * HID) / 256, blk>>>();
    fixup_kernel<<<512, 128>>>(x, w1);

    // fc2: out = spk @ w2^T  (2 fp16 split products folded into K=4096)
    hgemm<<<dim3(N2 / BN, M1 / BM), blk, SMEM_TOTAL>>>(a2, b2, out, N2, KE2, INV_WSCALE);

    write_rate_kernel<<<1, 1>>>(out, out_size - 1);
}

// round 6
// speedup vs baseline: 2.8403x; 1.3384x over previous
#include <cuda_runtime.h>
#include <cuda_fp16.h>
#include <cstdint>
#include <cstddef>

// Problem dims (fixed)
#define M1 16384      // b*t*s = 16*4*256
#define K1 512        // d
#define N1 2048       // hidden
#define N2 512
#define HID 2048
#define N_SPIKES 33554432.0f  // 2^25

#define TAU 4e-3f     // borderline window; sigma_v ~ 4e-4 -> 10 sigma margin
#define FCAP (1 << 22)

// ---------------------------------------------------------------------------
// Device scratch (no allocation allowed)
// ---------------------------------------------------------------------------
__device__ float  g_h[(size_t)M1 * N1];       // fc1 output (approx h, fp32)
__device__ __half g_x16[(size_t)M1 * K1];     // fp16(x)
__device__ __half g_w1h[(size_t)N1 * K1];     // fp16(w1)
__device__ __half g_spk[(size_t)M1 * HID];    // spikes (exact in fp16)
__device__ __half g_w2h[(size_t)N2 * HID];    // fp16(w2)
__device__ int    g_count;
__device__ int    g_nflag;
__device__ int    g_flag[FCAP];

// ---------------------------------------------------------------------------
// PTX helpers (baseline sm_80+ ISA: cp.async / ldmatrix / mma.sync)
// ---------------------------------------------------------------------------
__device__ __forceinline__ uint32_t smem_u32(const void* p) {
    uint32_t a;
    asm("{ .reg .u64 t; cvta.to.shared.u64 t, %1; cvt.u32.u64 %0, t; }" : "=r"(a) : "l"(p));
    return a;
}
__device__ __forceinline__ void cp16(uint32_t saddr, const void* g) {
    asm volatile("cp.async.cg.shared.global [%0], [%1], 16;" :: "r"(saddr), "l"(g));
}
__device__ __forceinline__ void ldm_x4(uint32_t* r, uint32_t addr) {
    asm volatile("ldmatrix.sync.aligned.m8n8.x4.shared.b16 {%0,%1,%2,%3}, [%4];"
        : "=r"(r[0]), "=r"(r[1]), "=r"(r[2]), "=r"(r[3]) : "r"(addr));
}
__device__ __forceinline__ void mma16816(float* c, const uint32_t* a, uint32_t b0, uint32_t b1) {
    asm volatile("mma.sync.aligned.m16n8k16.row.col.f32.f16.f16.f32 "
        "{%0,%1,%2,%3}, {%4,%5,%6,%7}, {%8,%9}, {%0,%1,%2,%3};"
        : "+f"(c[0]), "+f"(c[1]), "+f"(c[2]), "+f"(c[3])
        : "r"(a[0]), "r"(a[1]), "r"(a[2]), "r"(a[3]), "r"(b0), "r"(b1));
}

// ---------------------------------------------------------------------------
// HGEMM (NT): C[M,N] = A[M,K] @ B[N,K]^T, fp16 in / fp32 out.
// 128x128x64 tiles, 3-stage cp.async pipeline, 8 warps (32x64 per warp).
// ---------------------------------------------------------------------------
#define BM 128
#define BN 128
#define BK 64
#define STAGES 3
#define A_STAGE_BYTES (BM * BK * 2)                 // 16384
#define STAGE_BYTES   (A_STAGE_BYTES + BN * BK * 2) // 32768
#define SMEM_TOTAL    (STAGES * STAGE_BYTES)        // 98304

__device__ __forceinline__ void load_stage(uint32_t s_stage, const __half* Ag,
                                           const __half* Bg, int K, int k0, int tid) {
#pragma unroll
    for (int i = 0; i < 4; i++) {
        int c = tid + i * 256;           // 0..1023
        int row = c >> 3, kc = c & 7;
        uint32_t so = s_stage + row * 128 + ((kc ^ (row & 7)) << 4);
        cp16(so, Ag + (long)row * K + k0 + kc * 8);
    }
#pragma unroll
    for (int i = 0; i < 4; i++) {
        int c = tid + i * 256;
        int row = c >> 3, kc = c & 7;
        uint32_t so = s_stage + A_STAGE_BYTES + row * 128 + ((kc ^ (row & 7)) << 4);
        cp16(so, Bg + (long)row * K + k0 + kc * 8);
    }
}

__global__ __launch_bounds__(256, 2) void hgemm(const __half* __restrict__ A,
                                                const __half* __restrict__ B,
                                                float* __restrict__ C,
                                                int N, int K) {
    extern __shared__ char sm[];
    const uint32_t s_base = smem_u32(sm);
    const int tid = threadIdx.x;
    const int wid = tid >> 5, lane = tid & 31;
    const int wm = wid & 3;          // warp row block (32 rows)
    const int wn = wid >> 2;         // warp col block (64 cols)
    const long bm = (long)blockIdx.y * BM;
    const long bn = (long)blockIdx.x * BN;

    const __half* Ag = A + bm * K;
    const __half* Bg = B + bn * K;

    float acc[2][8][4];
#pragma unroll
    for (int mt = 0; mt < 2; mt++)
#pragma unroll
        for (int nt = 0; nt < 8; nt++)
#pragma unroll
            for (int i = 0; i < 4; i++) acc[mt][nt][i] = 0.0f;

    const int iters = K / BK;

    load_stage(s_base, Ag, Bg, K, 0, tid);
    asm volatile("cp.async.commit_group;" ::: "memory");
    load_stage(s_base + STAGE_BYTES, Ag, Bg, K, BK, tid);
    asm volatile("cp.async.commit_group;" ::: "memory");

    for (int it = 0; it < iters; it++) {
        asm volatile("cp.async.wait_group 1;" ::: "memory");
        __syncthreads();

        const int nst = it + 2;
        if (nst < iters)
            load_stage(s_base + (nst % STAGES) * STAGE_BYTES, Ag, Bg, K, nst * BK, tid);
        asm volatile("cp.async.commit_group;" ::: "memory");

        const uint32_t sa = s_base + (it % STAGES) * STAGE_BYTES;
        const uint32_t sb = sa + A_STAGE_BYTES;

#pragma unroll
        for (int ks = 0; ks < 4; ks++) {
            const int kch = (ks << 1) + (lane >> 4);   // k16-step -> 8-elem chunk
            uint32_t ar[2][4];
#pragma unroll
            for (int mt = 0; mt < 2; mt++) {
                int row = wm * 32 + mt * 16 + (lane & 15);
                ldm_x4(ar[mt], sa + row * 128 + ((kch ^ (row & 7)) << 4));
            }
            uint32_t br[4][4];
#pragma unroll
            for (int np = 0; np < 4; np++) {
                int row = wn * 64 + np * 16 + (lane & 15);
                ldm_x4(br[np], sb + row * 128 + ((kch ^ (row & 7)) << 4));
            }
#pragma unroll
            for (int mt = 0; mt < 2; mt++)
#pragma unroll
                for (int nt = 0; nt < 8; nt++)
                    mma16816(acc[mt][nt], ar[mt], br[nt >> 1][nt & 1], br[nt >> 1][(nt & 1) + 2]);
        }
    }

    // epilogue: fp32 stores
#pragma unroll
    for (int mt = 0; mt < 2; mt++) {
#pragma unroll
        for (int nt = 0; nt < 8; nt++) {
            long r = bm + wm * 32 + mt * 16 + (lane >> 2);
            long c = bn + wn * 64 + nt * 8 + (lane & 3) * 2;
            *(float2*)(C + r * N + c) = make_float2(acc[mt][nt][0], acc[mt][nt][1]);
            *(float2*)(C + (r + 8) * N + c) = make_float2(acc[mt][nt][2], acc[mt][nt][3]);
        }
    }
}

// ---------------------------------------------------------------------------
// fp32 -> fp16 cast (vectorized, 4 elems/thread)
// ---------------------------------------------------------------------------
__global__ __launch_bounds__(256) void cast16_kernel(const float* __restrict__ in,
                                                     __half* __restrict__ out, int n4) {
    int i = blockIdx.x * blockDim.x + threadIdx.x;
    if (i >= n4) return;
    float4 v = ((const float4*)in)[i];
    __half2 h01 = __floats2half2_rn(v.x, v.y);
    __half2 h23 = __floats2half2_rn(v.z, v.w);
    ((__half2*)out)[2 * i]     = h01;
    ((__half2*)out)[2 * i + 1] = h23;
}

// ---------------------------------------------------------------------------
// LIF scan (t=4) on approx h, with borderline flagging.
// Unflagged decisions are provably exact (|v-1| >= TAU >> delta_v).
// ---------------------------------------------------------------------------
__global__ void zero_count_kernel() { g_count = 0; g_nflag = 0; }

__global__ __launch_bounds__(256) void lif_kernel() {
    int idx = blockIdx.x * blockDim.x + threadIdx.x;   // 0 .. 4096*2048-1
    int j   = idx & (HID - 1);
    int row = idx >> 11;
    int b   = row >> 8;
    int s   = row & 255;
    size_t base = ((size_t)b * 1024 + s) * HID + j;    // (b, t=0, s) position
    const size_t tstride = (size_t)256 * HID;

    const __half one  = __float2half_rn(1.0f);
    const __half zero = __float2half_rn(0.0f);

    float v = 0.0f;
    int c = 0;
    bool flagged = false;
#pragma unroll
    for (int tt = 0; tt < 4; tt++) {
        float inp = g_h[base + tt * tstride];
        v = fmaf(0.95f, v, inp);
        flagged |= fabsf(v - 1.0f) < TAU;
        bool fire = (v - 1.0f) > 0.0f;
        g_spk[base + tt * tstride] = fire ? one : zero;
        c += fire ? 1 : 0;
        v = fire ? 0.0f : v;
    }
    if (flagged) {
        c = 0;  // counted exactly in fixup
        int slot = atomicAdd(&g_nflag, 1);
        if (slot < FCAP) g_flag[slot] = idx;
    }
#pragma unroll
    for (int o = 16; o > 0; o >>= 1) c += __shfl_down_sync(0xffffffffu, c, o);
    if ((threadIdx.x & 31) == 0 && c) atomicAdd(&g_count, c);
}

// ---------------------------------------------------------------------------
// Exact fixup for flagged neurons: bit-identical arithmetic to the R1 kernel
// (sequential ascending-k fp32 fmaf), which produced 0 flips vs reference.
// ---------------------------------------------------------------------------
__global__ __launch_bounds__(128) void fixup_kernel(const float* __restrict__ x,
                                                    const float* __restrict__ w1) {
    int n = g_nflag;
    if (n > FCAP) n = FCAP;
    const int stride = gridDim.x * blockDim.x;
    const __half one  = __float2half_rn(1.0f);
    const __half zero = __float2half_rn(0.0f);

    for (int i = blockIdx.x * blockDim.x + threadIdx.x; i < n; i += stride) {
        int idx = g_flag[i];
        int j   = idx & (HID - 1);
        int row = idx >> 11;
        int b   = row >> 8;
        int s   = row & 255;
        const float4* wrow = (const float4*)(w1 + (size_t)j * K1);
        size_t base = ((size_t)b * 1024 + s) * HID + j;
        const size_t tstride = (size_t)256 * HID;

        float v = 0.0f;
        int c = 0;
#pragma unroll
        for (int tt = 0; tt < 4; tt++) {
            const float4* xrow = (const float4*)(x + (((size_t)b * 4 + tt) * 256 + s) * K1);
            float h = 0.0f;
            for (int k = 0; k < K1 / 4; k++) {
                float4 xv = __ldg(xrow + k);
                float4 wv = __ldg(wrow + k);
                h = fmaf(xv.x, wv.x, h);
                h = fmaf(xv.y, wv.y, h);
                h = fmaf(xv.z, wv.z, h);
                h = fmaf(xv.w, wv.w, h);
            }
            v = fmaf(0.95f, v, h);
            bool fire = (v - 1.0f) > 0.0f;
            g_spk[base + tt * tstride] = fire ? one : zero;
            c += fire ? 1 : 0;
            v = fire ? 0.0f : v;
        }
        if (c) atomicAdd(&g_count, c);
    }
}

__global__ void write_rate_kernel(float* __restrict__ out, int pos) {
    out[pos] = (float)g_count * (1.0f / N_SPIKES);  // exact: count / 2^25
}

// ---------------------------------------------------------------------------
extern "C" void kernel_launch(void* const* d_in, const int* in_sizes, int n_in,
                              void* d_out, int out_size) {
    const float* x  = (const float*)d_in[0];  // (16,4,256,512)
    const float* w1 = (const float*)d_in[1];  // (2048,512)
    const float* w2 = (const float*)d_in[2];  // (512,2048)
    float* out = (float*)d_out;

    float* h_ptr = nullptr;
    __half *x16, *w1h, *spk, *w2h;
    cudaGetSymbolAddress((void**)&h_ptr, g_h);
    cudaGetSymbolAddress((void**)&x16, g_x16);
    cudaGetSymbolAddress((void**)&w1h, g_w1h);
    cudaGetSymbolAddress((void**)&spk, g_spk);
    cudaGetSymbolAddress((void**)&w2h, g_w2h);

    cudaFuncSetAttribute(hgemm, cudaFuncAttributeMaxDynamicSharedMemorySize, SMEM_TOTAL);

    dim3 blk(256);

    // fp16 casts (single product per GEMM; fixup absorbs the quantization error)
    cast16_kernel<<<(M1 * K1 / 4 + 255) / 256, blk>>>(x, x16, M1 * K1 / 4);
    cast16_kernel<<<(N1 * K1 / 4 + 255) / 256, blk>>>(w1, w1h, N1 * K1 / 4);
    cast16_kernel<<<(N2 * HID / 4 + 255) / 256, blk>>>(w2, w2h, N2 * HID / 4);

    // fc1: approx h = x16 @ w1h^T  (K=512)
    hgemm<<<dim3(N1 / BN, M1 / BM), blk, SMEM_TOTAL>>>(x16, w1h, h_ptr, N1, K1);

    // LIF scan (flags borderline neurons) + exact fixup for flagged ones
    zero_count_kernel<<<1, 1>>>();
    lif_kernel<<<(4096 * HID) / 256, blk>>>();
    fixup_kernel<<<512, 128>>>(x, w1);

    // fc2: out = spk @ w2h^T  (K=2048; spikes exact in fp16)
    hgemm<<<dim3(N2 / BN, M1 / BM), blk, SMEM_TOTAL>>>(spk, w2h, out, N2, HID);

    write_rate_kernel<<<1, 1>>>(out, out_size - 1);
}

// round 8
// speedup vs baseline: 4.0121x; 1.4126x over previous
#include <cuda_runtime.h>
#include <cuda_fp16.h>
#include <cstdint>
#include <cstddef>

// Problem dims (fixed)
#define M1 16384      // b*t*s = 16*4*256
#define K1 512        // d
#define N1 2048       // hidden
#define N2 512
#define HID 2048
#define N_SPIKES 33554432.0f  // 2^25

#define TAU 4e-3f     // borderline window; sigma_v ~ 4e-4 -> 10 sigma margin
#define FCAP (1 << 22)

// ---------------------------------------------------------------------------
// Device scratch (no allocation allowed). NOTE: no g_h — LIF is fused in fc1.
// Row order for x16 / spk is PERMUTED: row' = (b*256 + s)*4 + t.
// ---------------------------------------------------------------------------
__device__ __half g_x16[(size_t)M1 * K1];     // fp16(x), (b,s,t) row order
__device__ __half g_w1h[(size_t)N1 * K1];     // fp16(w1)
__device__ __half g_spk[(size_t)M1 * HID];    // spikes (fp16), (b,s,t) row order
__device__ __half g_w2h[(size_t)N2 * HID];    // fp16(w2)
__device__ int    g_count;
__device__ int    g_nflag;
__device__ int    g_flag[FCAP];

// ---------------------------------------------------------------------------
// PTX helpers (baseline sm_80+ ISA: cp.async / ldmatrix / mma.sync)
// ---------------------------------------------------------------------------
__device__ __forceinline__ uint32_t smem_u32(const void* p) {
    uint32_t a;
    asm("{ .reg .u64 t; cvta.to.shared.u64 t, %1; cvt.u32.u64 %0, t; }" : "=r"(a) : "l"(p));
    return a;
}
__device__ __forceinline__ void cp16(uint32_t saddr, const void* g) {
    asm volatile("cp.async.cg.shared.global [%0], [%1], 16;" :: "r"(saddr), "l"(g));
}
__device__ __forceinline__ void ldm_x4(uint32_t* r, uint32_t addr) {
    asm volatile("ldmatrix.sync.aligned.m8n8.x4.shared.b16 {%0,%1,%2,%3}, [%4];"
        : "=r"(r[0]), "=r"(r[1]), "=r"(r[2]), "=r"(r[3]) : "r"(addr));
}
__device__ __forceinline__ void mma16816(float* c, const uint32_t* a, uint32_t b0, uint32_t b1) {
    asm volatile("mma.sync.aligned.m16n8k16.row.col.f32.f16.f16.f32 "
        "{%0,%1,%2,%3}, {%4,%5,%6,%7}, {%8,%9}, {%0,%1,%2,%3};"
        : "+f"(c[0]), "+f"(c[1]), "+f"(c[2]), "+f"(c[3])
        : "r"(a[0]), "r"(a[1]), "r"(a[2]), "r"(a[3]), "r"(b0), "r"(b1));
}

// ---------------------------------------------------------------------------
// Shared GEMM core: 128x128x64 tiles, 3-stage cp.async, 8 warps (32x64/warp)
// ---------------------------------------------------------------------------
#define BM 128
#define BN 128
#define BK 64
#define STAGES 3
#define A_STAGE_BYTES (BM * BK * 2)                 // 16384
#define STAGE_BYTES   (A_STAGE_BYTES + BN * BK * 2) // 32768
#define SMEM_TOTAL    (STAGES * STAGE_BYTES)        // 98304 (>= 128*132*4 epi)

__device__ __forceinline__ void load_stage(uint32_t s_stage, const __half* Ag,
                                           const __half* Bg, int K, int k0, int tid) {
#pragma unroll
    for (int i = 0; i < 4; i++) {
        int c = tid + i * 256;
        int row = c >> 3, kc = c & 7;
        uint32_t so = s_stage + row * 128 + ((kc ^ (row & 7)) << 4);
        cp16(so, Ag + (long)row * K + k0 + kc * 8);
    }
#pragma unroll
    for (int i = 0; i < 4; i++) {
        int c = tid + i * 256;
        int row = c >> 3, kc = c & 7;
        uint32_t so = s_stage + A_STAGE_BYTES + row * 128 + ((kc ^ (row & 7)) << 4);
        cp16(so, Bg + (long)row * K + k0 + kc * 8);
    }
}

// Mainloop macro body shared by both kernels (acc in caller scope)
#define GEMM_MAINLOOP(Ag, Bg, K)                                                   \
    const int iters = (K) / BK;                                                    \
    load_stage(s_base, Ag, Bg, K, 0, tid);                                         \
    asm volatile("cp.async.commit_group;" ::: "memory");                           \
    load_stage(s_base + STAGE_BYTES, Ag, Bg, K, BK, tid);                          \
    asm volatile("cp.async.commit_group;" ::: "memory");                           \
    for (int it = 0; it < iters; it++) {                                           \
        asm volatile("cp.async.wait_group 1;" ::: "memory");                       \
        __syncthreads();                                                           \
        const int nst = it + 2;                                                    \
        if (nst < iters)                                                           \
            load_stage(s_base + (nst % STAGES) * STAGE_BYTES, Ag, Bg, K, nst * BK, tid); \
        asm volatile("cp.async.commit_group;" ::: "memory");                       \
        const uint32_t sa = s_base + (it % STAGES) * STAGE_BYTES;                  \
        const uint32_t sb = sa + A_STAGE_BYTES;                                    \
        _Pragma("unroll")                                                          \
        for (int ks = 0; ks < 4; ks++) {                                           \
            const int kch = (ks << 1) + (lane >> 4);                               \
            uint32_t ar[2][4];                                                     \
            _Pragma("unroll")                                                      \
            for (int mt = 0; mt < 2; mt++) {                                       \
                int row = wm * 32 + mt * 16 + (lane & 15);                         \
                ldm_x4(ar[mt], sa + row * 128 + ((kch ^ (row & 7)) << 4));         \
            }                                                                      \
            uint32_t br[4][4];                                                     \
            _Pragma("unroll")                                                      \
            for (int np = 0; np < 4; np++) {                                       \
                int row = wn * 64 + np * 16 + (lane & 15);                         \
                ldm_x4(br[np], sb + row * 128 + ((kch ^ (row & 7)) << 4));         \
            }                                                                      \
            _Pragma("unroll")                                                      \
            for (int mt = 0; mt < 2; mt++)                                         \
                _Pragma("unroll")                                                  \
                for (int nt = 0; nt < 8; nt++)                                     \
                    mma16816(acc[mt][nt], ar[mt], br[nt >> 1][nt & 1],             \
                             br[nt >> 1][(nt & 1) + 2]);                           \
        }                                                                          \
    }

// ---------------------------------------------------------------------------
// fc1 + fused LIF: A rows are (b,s,t)-ordered, so all 4 timesteps of a neuron
// live in this CTA tile. Epilogue: acc -> smem -> scan over t -> spikes+flags.
// ---------------------------------------------------------------------------
__global__ __launch_bounds__(256, 2) void hgemm_fc1_lif(const __half* __restrict__ A,
                                                        const __half* __restrict__ B) {
    extern __shared__ char sm[];
    const uint32_t s_base = smem_u32(sm);
    const int tid = threadIdx.x;
    const int wid = tid >> 5, lane = tid & 31;
    const int wm = wid & 3;
    const int wn = wid >> 2;
    const long bm = (long)blockIdx.y * BM;
    const long bn = (long)blockIdx.x * BN;

    const __half* Ag = A + bm * K1;
    const __half* Bg = B + bn * K1;

    float acc[2][8][4];
#pragma unroll
    for (int mt = 0; mt < 2; mt++)
#pragma unroll
        for (int nt = 0; nt < 8; nt++)
#pragma unroll
            for (int i = 0; i < 4; i++) acc[mt][nt][i] = 0.0f;

    GEMM_MAINLOOP(Ag, Bg, K1)

    // drain all cp.async before repurposing smem
    asm volatile("cp.async.wait_group 0;" ::: "memory");
    __syncthreads();

    // spill accumulators to smem: h[row within tile][col within tile]
    float* smf = (float*)sm;                 // [128][132]
#pragma unroll
    for (int mt = 0; mt < 2; mt++)
#pragma unroll
        for (int nt = 0; nt < 8; nt++) {
            int r0 = wm * 32 + mt * 16 + (lane >> 2);
            int c  = wn * 64 + nt * 8 + (lane & 3) * 2;
            smf[r0 * 132 + c]       = acc[mt][nt][0];
            smf[r0 * 132 + c + 1]   = acc[mt][nt][1];
            smf[(r0 + 8) * 132 + c]     = acc[mt][nt][2];
            smf[(r0 + 8) * 132 + c + 1] = acc[mt][nt][3];
        }
    __syncthreads();

    // LIF scan: 32 groups x 128 cols = 4096 scans, 16 per thread
    const __half one  = __float2half_rn(1.0f);
    const __half zero = __float2half_rn(0.0f);
    int total = 0;
#pragma unroll
    for (int k16 = 0; k16 < 16; k16++) {
        int id = tid + k16 * 256;
        int q  = id >> 7;             // group within tile (0..31)
        int c  = id & 127;            // col within tile
        long gq = blockIdx.y * 32 + q;        // global (b*256+s)
        long j  = bn + c;                     // hidden index

        float v = 0.0f;
        int cnt = 0;
        bool flagged = false;
#pragma unroll
        for (int t = 0; t < 4; t++) {
            float h = smf[(4 * q + t) * 132 + c];
            v = fmaf(0.95f, v, h);
            flagged |= fabsf(v - 1.0f) < TAU;
            bool fire = (v - 1.0f) > 0.0f;
            g_spk[(gq * 4 + t) * HID + j] = fire ? one : zero;
            cnt += fire ? 1 : 0;
            v = fire ? 0.0f : v;
        }
        if (flagged) {
            int slot = atomicAdd(&g_nflag, 1);
            if (slot < FCAP) g_flag[slot] = (int)(gq * 2048 + j);
        } else {
            total += cnt;
        }
    }
#pragma unroll
    for (int o = 16; o > 0; o >>= 1) total += __shfl_down_sync(0xffffffffu, total, o);
    if (lane == 0 && total) atomicAdd(&g_count, total);
}

// ---------------------------------------------------------------------------
// fc2: A = spikes in (b,s,t) row order; epilogue un-permutes to (b,t,s) rows.
// ---------------------------------------------------------------------------
__global__ __launch_bounds__(256, 2) void hgemm_fc2(const __half* __restrict__ A,
                                                    const __half* __restrict__ B,
                                                    float* __restrict__ C) {
    extern __shared__ char sm[];
    const uint32_t s_base = smem_u32(sm);
    const int tid = threadIdx.x;
    const int wid = tid >> 5, lane = tid & 31;
    const int wm = wid & 3;
    const int wn = wid >> 2;
    const long bm = (long)blockIdx.y * BM;
    const long bn = (long)blockIdx.x * BN;

    const __half* Ag = A + bm * HID;
    const __half* Bg = B + bn * HID;

    float acc[2][8][4];
#pragma unroll
    for (int mt = 0; mt < 2; mt++)
#pragma unroll
        for (int nt = 0; nt < 8; nt++)
#pragma unroll
            for (int i = 0; i < 4; i++) acc[mt][nt][i] = 0.0f;

    GEMM_MAINLOOP(Ag, Bg, HID)

    // epilogue: map row' (b,s,t) -> out row (b,t,s)
#pragma unroll
    for (int mt = 0; mt < 2; mt++)
#pragma unroll
        for (int nt = 0; nt < 8; nt++) {
            long rp0 = bm + wm * 32 + mt * 16 + (lane >> 2);
            long rp1 = rp0 + 8;
            long c = bn + wn * 64 + nt * 8 + (lane & 3) * 2;
            long b0 = rp0 >> 10, s0 = (rp0 >> 2) & 255, t0 = rp0 & 3;
            long b1 = rp1 >> 10, s1 = (rp1 >> 2) & 255, t1 = rp1 & 3;
            long r0 = b0 * 1024 + t0 * 256 + s0;
            long r1 = b1 * 1024 + t1 * 256 + s1;
            *(float2*)(C + r0 * N2 + c) = make_float2(acc[mt][nt][0], acc[mt][nt][1]);
            *(float2*)(C + r1 * N2 + c) = make_float2(acc[mt][nt][2], acc[mt][nt][3]);
        }
}

// ---------------------------------------------------------------------------
// Casts. x cast also permutes rows (b,t,s) -> (b,s,t).
// ---------------------------------------------------------------------------
__global__ __launch_bounds__(256) void cast_x_perm_kernel(const float* __restrict__ x,
                                                          __half* __restrict__ out) {
    int i4 = blockIdx.x * blockDim.x + threadIdx.x;   // over M1*K1/4 float4s
    if (i4 >= M1 * K1 / 4) return;
    int row = i4 >> 7;            // 128 float4 per row (K1=512)
    int within = i4 & 127;
    int b = row >> 10, t = (row >> 8) & 3, s = row & 255;
    long newrow = (((long)b * 256 + s) * 4 + t);
    float4 v = ((const float4*)x)[i4];
    __half2* dst = (__half2*)(out + newrow * K1 + within * 4);
    dst[0] = __floats2half2_rn(v.x, v.y);
    dst[1] = __floats2half2_rn(v.z, v.w);
}

__global__ __launch_bounds__(256) void cast16_kernel(const float* __restrict__ in,
                                                     __half* __restrict__ out, int n4) {
    int i = blockIdx.x * blockDim.x + threadIdx.x;
    if (i >= n4) return;
    float4 v = ((const float4*)in)[i];
    ((__half2*)out)[2 * i]     = __floats2half2_rn(v.x, v.y);
    ((__half2*)out)[2 * i + 1] = __floats2half2_rn(v.z, v.w);
}

__global__ void zero_count_kernel() { g_count = 0; g_nflag = 0; }

// ---------------------------------------------------------------------------
// Exact fixup for flagged neurons (bit-identical to R1's 0-flip arithmetic).
// flag encodes gq*2048 + j with gq = b*256 + s.
// ---------------------------------------------------------------------------
__global__ __launch_bounds__(128) void fixup_kernel(const float* __restrict__ x,
                                                    const float* __restrict__ w1) {
    int n = g_nflag;
    if (n > FCAP) n = FCAP;
    const int stride = gridDim.x * blockDim.x;
    const __half one  = __float2half_rn(1.0f);
    const __half zero = __float2half_rn(0.0f);

    for (int i = blockIdx.x * blockDim.x + threadIdx.x; i < n; i += stride) {
        int idx = g_flag[i];
        int j  = idx & (HID - 1);
        int gq = idx >> 11;           // b*256 + s
        int b  = gq >> 8;
        int s  = gq & 255;
        const float4* wrow = (const float4*)(w1 + (size_t)j * K1);

        float v = 0.0f;
        int c = 0;
#pragma unroll
        for (int tt = 0; tt < 4; tt++) {
            const float4* xrow = (const float4*)(x + (((size_t)b * 4 + tt) * 256 + s) * K1);
            float h = 0.0f;
            for (int k = 0; k < K1 / 4; k++) {
                float4 xv = __ldg(xrow + k);
                float4 wv = __ldg(wrow + k);
                h = fmaf(xv.x, wv.x, h);
                h = fmaf(xv.y, wv.y, h);
                h = fmaf(xv.z, wv.z, h);
                h = fmaf(xv.w, wv.w, h);
            }
            v = fmaf(0.95f, v, h);
            bool fire = (v - 1.0f) > 0.0f;
            g_spk[((size_t)gq * 4 + tt) * HID + j] = fire ? one : zero;
            c += fire ? 1 : 0;
            v = fire ? 0.0f : v;
        }
        if (c) atomicAdd(&g_count, c);
    }
}

__global__ void write_rate_kernel(float* __restrict__ out, int pos) {
    out[pos] = (float)g_count * (1.0f / N_SPIKES);  // exact: count / 2^25
}

// ---------------------------------------------------------------------------
extern "C" void kernel_launch(void* const* d_in, const int* in_sizes, int n_in,
                              void* d_out, int out_size) {
    const float* x  = (const float*)d_in[0];  // (16,4,256,512)
    const float* w1 = (const float*)d_in[1];  // (2048,512)
    const float* w2 = (const float*)d_in[2];  // (512,2048)
    float* out = (float*)d_out;

    __half *x16, *w1h, *spk, *w2h;
    cudaGetSymbolAddress((void**)&x16, g_x16);
    cudaGetSymbolAddress((void**)&w1h, g_w1h);
    cudaGetSymbolAddress((void**)&spk, g_spk);
    cudaGetSymbolAddress((void**)&w2h, g_w2h);

    cudaFuncSetAttribute(hgemm_fc1_lif, cudaFuncAttributeMaxDynamicSharedMemorySize, SMEM_TOTAL);
    cudaFuncSetAttribute(hgemm_fc2, cudaFuncAttributeMaxDynamicSharedMemorySize, SMEM_TOTAL);

    dim3 blk(256);

    zero_count_kernel<<<1, 1>>>();

    // fp16 casts (x also row-permuted to (b,s,t))
    cast_x_perm_kernel<<<(M1 * K1 / 4 + 255) / 256, blk>>>(x, x16);
    cast16_kernel<<<(N1 * K1 / 4 + 255) / 256, blk>>>(w1, w1h, N1 * K1 / 4);
    cast16_kernel<<<(N2 * HID / 4 + 255) / 256, blk>>>(w2, w2h, N2 * HID / 4);

    // fc1 + fused LIF scan (writes spikes + flags; counts unflagged spikes)
    hgemm_fc1_lif<<<dim3(N1 / BN, M1 / BM), blk, SMEM_TOTAL>>>(x16, w1h);

    // exact fixup for flagged neurons
    fixup_kernel<<<512, 128>>>(x, w1);

    // fc2: out = spk @ w2h^T  (row un-permutation in epilogue)
    hgemm_fc2<<<dim3(N2 / BN, M1 / BM), blk, SMEM_TOTAL>>>(spk, w2h, out);

    write_rate_kernel<<<1, 1>>>(out, out_size - 1);
}